// round 11
// baseline (speedup 1.0000x reference)
#include <cuda_runtime.h>
#include <cuda_fp16.h>
#include <math.h>
#include <stdint.h>

// ---------------------------------------------------------------------------
#define D        256
#define N_NODES  4000
#define LL       3
#define VV       2

#define Q_ROWS     8640
#define TOTAL_ROWS 10800
#define N_ANCHORS  1440

#define PROJ_BLOCKS 169     // ceil(10800 / 64)
#define ROWS_PB     64
#define APITCH      264     // A tile pitch in halfs (528 B rows)
#define WPB         272     // W half-tile pitch in BYTES (256B data + 16B pad)

#define LOSS_BLOCKS 168

__device__ unsigned int g_projh[(size_t)TOTAL_ROWS * 128];  // fp16 proj rows
__device__ unsigned int g_Wh[2][32768];                     // fp16 W, row-major [n][k/2]
__device__ float g_pos[N_ANCHORS];
__device__ float g_neg[N_ANCHORS];
__device__ unsigned int g_ctr;

// ---------------------------------------------------------------------------
__device__ __forceinline__ uint32_t smem_u32(const void* p) {
    uint32_t a;
    asm("{ .reg .u64 t; cvta.to.shared.u64 t, %1; cvt.u32.u64 %0, t; }"
        : "=r"(a) : "l"(p));
    return a;
}
__device__ __forceinline__ void ldsm_x4(uint32_t* r, uint32_t addr) {
    asm volatile("ldmatrix.sync.aligned.m8n8.x4.shared.b16 {%0,%1,%2,%3}, [%4];"
                 : "=r"(r[0]), "=r"(r[1]), "=r"(r[2]), "=r"(r[3]) : "r"(addr));
}
__device__ __forceinline__ void ldsm_x2(uint32_t* r, uint32_t addr) {
    asm volatile("ldmatrix.sync.aligned.m8n8.x2.shared.b16 {%0,%1}, [%2];"
                 : "=r"(r[0]), "=r"(r[1]) : "r"(addr));
}
__device__ __forceinline__ void mma16816(float* c, const uint32_t* a,
                                         const uint32_t* b) {
    asm volatile("mma.sync.aligned.m16n8k16.row.col.f32.f16.f16.f32 "
                 "{%0,%1,%2,%3}, {%4,%5,%6,%7}, {%8,%9}, {%0,%1,%2,%3};"
                 : "+f"(c[0]), "+f"(c[1]), "+f"(c[2]), "+f"(c[3])
                 : "r"(a[0]), "r"(a[1]), "r"(a[2]), "r"(a[3]),
                   "r"(b[0]), "r"(b[1]));
}

// ---------------------------------------------------------------------------
// W fp32 -> fp16 row-major image; zero accumulators + finalize counter.
__global__ void __launch_bounds__(512) prep_w_kernel(const float* __restrict__ W1,
                                                     const float* __restrict__ W2)
{
    int i = blockIdx.x * 512 + threadIdx.x;    // 0..32767
    if (i < N_ANCHORS) { g_pos[i] = 0.f; g_neg[i] = 0.f; }
    if (i == 0) g_ctr = 0u;
    {
        __half2 h1 = __floats2half2_rn(W1[i * 2], W1[i * 2 + 1]);
        __half2 h2 = __floats2half2_rn(W2[i * 2], W2[i * 2 + 1]);
        g_Wh[0][i] = *reinterpret_cast<unsigned int*>(&h1);
        g_Wh[1][i] = *reinterpret_cast<unsigned int*>(&h2);
    }
}

// ---------------------------------------------------------------------------
__device__ __forceinline__ const float* map_src_row(
    int r, const float* __restrict__ E,
    const int* __restrict__ idxp, const int* __restrict__ idxr,
    const int* __restrict__ negp, const int* __restrict__ negr)
{
    if (r < Q_ROWS) {
        int t, local, S;
        if (r < 3600)      { t = 0; local = r;        S = 100; }
        else if (r < 7200) { t = 1; local = r - 3600; S = 100; }
        else if (r < 7920) { t = 2; local = r - 7200; S = 20;  }
        else               { t = 3; local = r - 7920; S = 20;  }
        int perxy = 6 * S;
        int xy  = local / perxy;
        int rem = local - xy * perxy;
        int node = (t < 2) ? idxp[t * 600 + rem] : idxr[(t - 2) * 120 + rem];
        int x = xy / LL, y = xy - x * LL;
        return E + ((size_t)(((t * VV + x) * LL + y) * N_NODES + node)) * D;
    } else {
        int rr = r - Q_ROWS;
        int t, local, K;
        if (rr < 900)       { t = 0; local = rr;        K = 50; }
        else if (rr < 1800) { t = 1; local = rr - 900;  K = 50; }
        else if (rr < 1980) { t = 2; local = rr - 1800; K = 10; }
        else                { t = 3; local = rr - 1980; K = 10; }
        int perO = 6 * K;
        int o   = local / perO;
        int vlk = local - o * perO;
        int vl  = vlk / K;
        int k   = vlk - vl * K;
        int off = (vl * 3 + o) * K + k;
        int node = (t < 2) ? negp[t * 900 + off] : negr[(t - 2) * 180 + off];
        int ot = o + (o >= t ? 1 : 0);
        int v = vl / LL, l = vl - v * LL;
        return E + ((size_t)(((ot * VV + v) * LL + l) * N_NODES + node)) * D;
    }
}

// ---------------------------------------------------------------------------
// Projection: 169 blocks x 512 thr (16 warps: 2 my x 8 cx), 64 rows/block,
// W staged as two K-halves (68KB buffer) -> ~105KB smem -> 2 blocks/SM.
#define SMA   0
#define SMW   33792                       // A: 64*264*2
#define CTRL  (SMW + 256 * WPB)           // 33792 + 69632 = 103424
#define SM_BYTES (CTRL + 1024 + 1024 + 512 + 2048)

__global__ void __launch_bounds__(512, 2)
proj_mma_kernel(const float* __restrict__ E,
                const float* __restrict__ b1, const float* __restrict__ b2,
                const int* __restrict__ idxp, const int* __restrict__ idxr,
                const int* __restrict__ negp, const int* __restrict__ negr)
{
    extern __shared__ char sm[];
    const uint32_t smb = smem_u32(sm);

    float* smb1 = (float*)(sm + CTRL);
    float* smb2 = (float*)(sm + CTRL + 1024);
    const float** srcp = (const float**)(sm + CTRL + 2048);
    float* ssbuf = (float*)(sm + CTRL + 2560);   // [64][8]

    const int tid = threadIdx.x;
    const int l   = tid & 31;
    const int w   = tid >> 5;
    const int my  = w >> 3;          // 0..1 (32 rows each)
    const int cx  = w & 7;           // 0..7 (32 cols each)
    const int r0  = blockIdx.x * ROWS_PB;

    if (tid < 64)        ((float4*)smb1)[tid]      = ((const float4*)b1)[tid];
    else if (tid < 128)  ((float4*)smb2)[tid - 64] = ((const float4*)b2)[tid - 64];
    if (tid < ROWS_PB) {
        int r = r0 + tid;
        srcp[tid] = (r < TOTAL_ROWS)
                  ? map_src_row(r, E, idxp, idxr, negp, negr)
                  : (const float*)0;
    }
    __syncthreads();   // srcp ready

    // gather X -> fp16 A tile (8 threads/row, 8 float4 each)
    for (int i = tid; i < ROWS_PB * 64; i += 512) {
        int m = i >> 6, q = i & 63;
        const float* s = srcp[m];
        float4 v = make_float4(0.f, 0.f, 0.f, 0.f);
        if (s) v = ((const float4*)s)[q];
        __half2 p0 = __floats2half2_rn(v.x, v.y);
        __half2 p1 = __floats2half2_rn(v.z, v.w);
        uint2 pk = make_uint2(*reinterpret_cast<unsigned int*>(&p0),
                              *reinterpret_cast<unsigned int*>(&p1));
        *(uint2*)(sm + SMA + (m * APITCH + q * 4) * 2) = pk;
    }

    const uint32_t a_base = smb + SMA +
        ((my * 32 + ((l >> 3) & 1) * 8 + (l & 7)) * APITCH + (l >> 4) * 8) * 2;
    const uint32_t b_base = smb + SMW +
        (cx * 32 + (l & 7)) * WPB + ((l >> 3) & 1) * 16;

    const int g  = l >> 2;
    const int q2 = (l & 3) * 2;

    float c[2][4][4];

    // ======================= two layers =======================
    #pragma unroll
    for (int layer = 0; layer < 2; layer++) {
        #pragma unroll
        for (int mt = 0; mt < 2; mt++)
            #pragma unroll
            for (int nt = 0; nt < 4; nt++)
                #pragma unroll
                for (int j = 0; j < 4; j++) c[mt][nt][j] = 0.f;

        #pragma unroll
        for (int kh = 0; kh < 2; kh++) {
            // stage W half: 256 rows x 16 float4
            for (int i = tid; i < 4096; i += 512) {
                int n = i >> 4, q = i & 15;
                *(float4*)(sm + SMW + n * WPB + q * 16) =
                    ((const float4*)g_Wh[layer])[n * 32 + kh * 16 + q];
            }
            __syncthreads();

            #pragma unroll
            for (int kk = 0; kk < 8; kk++) {
                int kk16 = kh * 8 + kk;
                uint32_t a[8];
                ldsm_x4(a,     a_base + kk16 * 32);
                ldsm_x4(a + 4, a_base + kk16 * 32 + 16 * APITCH * 2);
                #pragma unroll
                for (int nt = 0; nt < 4; nt++) {
                    uint32_t b[2];
                    ldsm_x2(b, b_base + kk * 32 + nt * 8 * WPB);
                    mma16816(c[0][nt], a,     b);
                    mma16816(c[1][nt], a + 4, b);
                }
            }
            __syncthreads();   // all reads of this W half done
        }

        if (layer == 0) {
            // epilogue 1: bias + relu -> fp16 H into A tile
            #pragma unroll
            for (int mt = 0; mt < 2; mt++) {
                #pragma unroll
                for (int nt = 0; nt < 4; nt++) {
                    int col = cx * 32 + nt * 8 + q2;
                    float bx = smb1[col], by = smb1[col + 1];
                    int rlo = my * 32 + mt * 16 + g;
                    __half2 lo = __floats2half2_rn(fmaxf(c[mt][nt][0] + bx, 0.f),
                                                   fmaxf(c[mt][nt][1] + by, 0.f));
                    __half2 hi = __floats2half2_rn(fmaxf(c[mt][nt][2] + bx, 0.f),
                                                   fmaxf(c[mt][nt][3] + by, 0.f));
                    *(unsigned int*)(sm + SMA + (rlo * APITCH + col) * 2) =
                        *reinterpret_cast<unsigned int*>(&lo);
                    *(unsigned int*)(sm + SMA + ((rlo + 8) * APITCH + col) * 2) =
                        *reinterpret_cast<unsigned int*>(&hi);
                }
            }
            __syncthreads();   // H complete before layer-2 ldsm
        }
    }

    // epilogue 2: bias, row L2-norm, fp16 store
    float ss[4] = {0.f, 0.f, 0.f, 0.f};
    #pragma unroll
    for (int mt = 0; mt < 2; mt++) {
        #pragma unroll
        for (int nt = 0; nt < 4; nt++) {
            int col = cx * 32 + nt * 8 + q2;
            float bx = smb2[col], by = smb2[col + 1];
            float z0 = c[mt][nt][0] + bx, z1 = c[mt][nt][1] + by;
            float z2 = c[mt][nt][2] + bx, z3 = c[mt][nt][3] + by;
            ss[mt * 2]     += z0 * z0 + z1 * z1;
            ss[mt * 2 + 1] += z2 * z2 + z3 * z3;
        }
    }
    #pragma unroll
    for (int j = 0; j < 4; j++) {
        ss[j] += __shfl_xor_sync(0xffffffffu, ss[j], 1);
        ss[j] += __shfl_xor_sync(0xffffffffu, ss[j], 2);
    }
    if ((l & 3) == 0) {
        #pragma unroll
        for (int j = 0; j < 4; j++) {
            int row = my * 32 + (j >> 1) * 16 + (j & 1) * 8 + g;
            ssbuf[row * 8 + cx] = ss[j];
        }
    }
    __syncthreads();

    float inv[4];
    #pragma unroll
    for (int j = 0; j < 4; j++) {
        int row = my * 32 + (j >> 1) * 16 + (j & 1) * 8 + g;
        float t = 0.f;
        #pragma unroll
        for (int c8 = 0; c8 < 8; c8++) t += ssbuf[row * 8 + c8];
        inv[j] = 1.0f / fmaxf(sqrtf(t), 1e-12f);
    }

    #pragma unroll
    for (int mt = 0; mt < 2; mt++) {
        #pragma unroll
        for (int nt = 0; nt < 4; nt++) {
            int col = cx * 32 + nt * 8 + q2;
            float bx = smb2[col], by = smb2[col + 1];
            int rlo = r0 + my * 32 + mt * 16 + g;
            int rhi = rlo + 8;
            int ci = (col >> 1);
            if (rlo < TOTAL_ROWS) {
                __half2 h = __floats2half2_rn((c[mt][nt][0] + bx) * inv[mt * 2],
                                              (c[mt][nt][1] + by) * inv[mt * 2]);
                g_projh[(size_t)rlo * 128 + ci] = *reinterpret_cast<unsigned int*>(&h);
            }
            if (rhi < TOTAL_ROWS) {
                __half2 h = __floats2half2_rn((c[mt][nt][2] + bx) * inv[mt * 2 + 1],
                                              (c[mt][nt][3] + by) * inv[mt * 2 + 1]);
                g_projh[(size_t)rhi * 128 + ci] = *reinterpret_cast<unsigned int*>(&h);
            }
        }
    }
}

// ---------------------------------------------------------------------------
// Loss (R9 measured-best): 168 blocks x 512 threads, M64 x N128 x K256.
#define LSMA 0
#define LSMB 34816
#define LTRG 102400
#define LSM_BYTES (LTRG + 512 + 512 + 128)

__global__ void __launch_bounds__(512)
loss_mma_kernel(float* __restrict__ out)
{
    extern __shared__ char sm[];
    const uint32_t smb = smem_u32(sm);
    int* targ  = (int*)(sm + LTRG);
    int* tinfo = (int*)(sm + LTRG + 512);

    const int tid = threadIdx.x;
    const int l   = tid & 31;
    const int w   = tid >> 5;
    const int my  = w >> 3;          // 0..1
    const int cx  = w & 7;           // 0..7
    const int b   = blockIdx.x;

    int S, K, vl, chunk, mtile, qbase, pbase, aid0;
    if (b < 144) {
        int t = b / 72, rem = b % 72;
        vl = rem / 12;
        int r2 = rem % 12;
        mtile = r2 / 6; chunk = r2 % 6;
        S = 100; K = 50;
        qbase = t * 3600; pbase = t * 900;
        aid0  = t * 600 + vl * 100;
    } else {
        int bs = b - 144;
        int t2 = bs / 12;
        int rem = bs % 12;
        vl = rem / 2; chunk = rem % 2; mtile = 0;
        S = 20; K = 10;
        qbase = 7200 + t2 * 720; pbase = 1800 + t2 * 180;
        aid0  = 1200 + t2 * 120 + vl * 20;
    }
    const int NTARG = 6 * S + 3 * K;
    const int diag_base = qbase + vl * 7 * S;
    const int mrow0 = mtile * 64;

    if (tid < 128) {
        int n = chunk * 128 + tid;
        int row = 0, info = 0;
        if (n < 6 * S) {
            int xy = n / S, ts = n - xy * S;
            row  = qbase + (xy * 6 + vl) * S + ts;
            info = ts | ((xy == vl) ? 0x10000 : 0) | 0x40000;
        } else if (n < NTARG) {
            int cc = n - 6 * S;
            int o = cc / K, k = cc - o * K;
            row  = Q_ROWS + pbase + (o * 6 + vl) * K + k;
            info = 0x20000 | 0x40000;
        }
        targ[tid]  = row;
        tinfo[tid] = info;
    }
    __syncthreads();

    for (int i = tid; i < 64 * 32; i += 512) {
        int r = i >> 5, q = i & 31;
        int gr = mrow0 + r;
        int arow = diag_base + (gr < S ? gr : 0);
        *(float4*)(sm + LSMA + (r * APITCH + q * 8) * 2) =
            ((const float4*)g_projh)[(size_t)arow * 32 + q];
    }
    for (int i = tid; i < 128 * 32; i += 512) {
        int r = i >> 5, q = i & 31;
        *(float4*)(sm + LSMB + (r * APITCH + q * 8) * 2) =
            ((const float4*)g_projh)[(size_t)targ[r] * 32 + q];
    }
    __syncthreads();

    const uint32_t a_base = smb + LSMA +
        ((my * 32 + ((l >> 3) & 1) * 8 + (l & 7)) * APITCH + (l >> 4) * 8) * 2;
    const uint32_t b_base = smb + LSMB +
        ((cx * 16 + (l & 7)) * APITCH + ((l >> 3) & 1) * 8) * 2;

    float c[2][2][4];
    #pragma unroll
    for (int mt = 0; mt < 2; mt++)
        #pragma unroll
        for (int nt = 0; nt < 2; nt++)
            #pragma unroll
            for (int j = 0; j < 4; j++) c[mt][nt][j] = 0.f;

    #pragma unroll 8
    for (int kk = 0; kk < 16; kk++) {
        uint32_t a[8];
        ldsm_x4(a,     a_base + kk * 32);
        ldsm_x4(a + 4, a_base + kk * 32 + 16 * APITCH * 2);
        #pragma unroll
        for (int nt = 0; nt < 2; nt++) {
            uint32_t bb[2];
            ldsm_x2(bb, b_base + kk * 32 + nt * 8 * APITCH * 2);
            mma16816(c[0][nt], a,     bb);
            mma16816(c[1][nt], a + 4, bb);
        }
    }

    const int g  = l >> 2;
    const int q2 = (l & 3) * 2;
    float pacc[4] = {0.f, 0.f, 0.f, 0.f};
    float nacc[4] = {0.f, 0.f, 0.f, 0.f};

    int rowg[4];
    #pragma unroll
    for (int s = 0; s < 4; s++)
        rowg[s] = mrow0 + my * 32 + (s >> 1) * 16 + (s & 1) * 8 + g;

    #pragma unroll
    for (int nt = 0; nt < 2; nt++) {
        #pragma unroll
        for (int jl = 0; jl < 2; jl++) {
            int info = tinfo[cx * 16 + nt * 8 + q2 + jl];
            if (info & 0x40000) {
                int ts = info & 0xFFFF;
                #pragma unroll
                for (int mt = 0; mt < 2; mt++) {
                    #pragma unroll
                    for (int jh = 0; jh < 2; jh++) {
                        int s = mt * 2 + jh;
                        if (rowg[s] < S) {
                            float e = __expf(2.0f * c[mt][nt][jh * 2 + jl]);
                            if (info & 0x20000)        nacc[s] += e;
                            else if (info & 0x10000) { if (ts != rowg[s]) nacc[s] += e; }
                            else if (ts == rowg[s])    pacc[s] += e;
                        }
                    }
                }
            }
        }
    }

    #pragma unroll
    for (int s = 0; s < 4; s++) {
        pacc[s] += __shfl_xor_sync(0xffffffffu, pacc[s], 1);
        pacc[s] += __shfl_xor_sync(0xffffffffu, pacc[s], 2);
        nacc[s] += __shfl_xor_sync(0xffffffffu, nacc[s], 1);
        nacc[s] += __shfl_xor_sync(0xffffffffu, nacc[s], 2);
    }
    if ((l & 3) == 0) {
        #pragma unroll
        for (int s = 0; s < 4; s++) {
            if (rowg[s] < S) {
                if (pacc[s] != 0.f) atomicAdd(&g_pos[aid0 + rowg[s]], pacc[s]);
                if (nacc[s] != 0.f) atomicAdd(&g_neg[aid0 + rowg[s]], nacc[s]);
            }
        }
    }

    // ---- fused finalize ----
    __shared__ unsigned int is_last;
    __threadfence();
    __syncthreads();
    if (tid == 0)
        is_last = (atomicAdd(&g_ctr, 1u) == (unsigned)(gridDim.x - 1));
    __syncthreads();
    if (is_last) {
        float loc = 0.f;
        for (int i = tid; i < N_ANCHORS; i += 512) {
            float p = g_pos[i], n = g_neg[i];
            loc += -logf(p / (p + n));
        }
        loc += __shfl_xor_sync(0xffffffffu, loc, 16);
        loc += __shfl_xor_sync(0xffffffffu, loc, 8);
        loc += __shfl_xor_sync(0xffffffffu, loc, 4);
        loc += __shfl_xor_sync(0xffffffffu, loc, 2);
        loc += __shfl_xor_sync(0xffffffffu, loc, 1);
        float* red = (float*)(sm + LTRG + 1024);
        if (l == 0) red[w] = loc;
        __syncthreads();
        if (w == 0) {
            float s = (l < 16) ? red[l] : 0.f;
            s += __shfl_xor_sync(0xffffffffu, s, 8);
            s += __shfl_xor_sync(0xffffffffu, s, 4);
            s += __shfl_xor_sync(0xffffffffu, s, 2);
            s += __shfl_xor_sync(0xffffffffu, s, 1);
            if (l == 0) out[0] = s * (1.0f / 1440.0f);
        }
    }
}

// ---------------------------------------------------------------------------
extern "C" void kernel_launch(void* const* d_in, const int* in_sizes, int n_in,
                              void* d_out, int out_size)
{
    const float* E    = (const float*)d_in[0];
    const float* W1   = (const float*)d_in[1];
    const float* b1   = (const float*)d_in[2];
    const float* W2   = (const float*)d_in[3];
    const float* b2   = (const float*)d_in[4];
    const int*   idxp = (const int*)d_in[5];
    const int*   idxr = (const int*)d_in[6];
    const int*   negp = (const int*)d_in[7];
    const int*   negr = (const int*)d_in[8];
    float* out = (float*)d_out;
    (void)in_sizes; (void)n_in; (void)out_size;

    cudaFuncSetAttribute(proj_mma_kernel,
                         cudaFuncAttributeMaxDynamicSharedMemorySize, SM_BYTES);
    cudaFuncSetAttribute(loss_mma_kernel,
                         cudaFuncAttributeMaxDynamicSharedMemorySize, LSM_BYTES);

    prep_w_kernel<<<64, 512>>>(W1, W2);
    proj_mma_kernel<<<PROJ_BLOCKS, 512, SM_BYTES>>>(E, b1, b2,
                                                    idxp, idxr, negp, negr);
    loss_mma_kernel<<<LOSS_BLOCKS, 512, LSM_BYTES>>>(out);
}

// round 12
// speedup vs baseline: 1.0393x; 1.0393x over previous
#include <cuda_runtime.h>
#include <cuda_fp16.h>
#include <math.h>
#include <stdint.h>

// ---------------------------------------------------------------------------
#define D        256
#define N_NODES  4000
#define LL       3
#define VV       2

#define Q_ROWS     8640
#define TOTAL_ROWS 10800
#define N_ANCHORS  1440

#define PROJ_BLOCKS 85      // ceil(10800 / 128)
#define ROWS_PB     128
#define APITCH      264     // A tile pitch in halfs
#define WPB         272     // W half-tile row pitch in bytes (256B data + 16 pad)

#define LOSS_BLOCKS 168

__device__ unsigned int g_projh[(size_t)TOTAL_ROWS * 128];  // fp16 proj rows
__device__ float g_pos[N_ANCHORS];
__device__ float g_neg[N_ANCHORS];
__device__ unsigned int g_ctr;

// ---------------------------------------------------------------------------
__device__ __forceinline__ uint32_t smem_u32(const void* p) {
    uint32_t a;
    asm("{ .reg .u64 t; cvta.to.shared.u64 t, %1; cvt.u32.u64 %0, t; }"
        : "=r"(a) : "l"(p));
    return a;
}
__device__ __forceinline__ void ldsm_x4(uint32_t* r, uint32_t addr) {
    asm volatile("ldmatrix.sync.aligned.m8n8.x4.shared.b16 {%0,%1,%2,%3}, [%4];"
                 : "=r"(r[0]), "=r"(r[1]), "=r"(r[2]), "=r"(r[3]) : "r"(addr));
}
__device__ __forceinline__ void ldsm_x2(uint32_t* r, uint32_t addr) {
    asm volatile("ldmatrix.sync.aligned.m8n8.x2.shared.b16 {%0,%1}, [%2];"
                 : "=r"(r[0]), "=r"(r[1]) : "r"(addr));
}
__device__ __forceinline__ void mma16816(float* c, const uint32_t* a,
                                         const uint32_t* b) {
    asm volatile("mma.sync.aligned.m16n8k16.row.col.f32.f16.f16.f32 "
                 "{%0,%1,%2,%3}, {%4,%5,%6,%7}, {%8,%9}, {%0,%1,%2,%3};"
                 : "+f"(c[0]), "+f"(c[1]), "+f"(c[2]), "+f"(c[3])
                 : "r"(a[0]), "r"(a[1]), "r"(a[2]), "r"(a[3]),
                   "r"(b[0]), "r"(b[1]));
}

// ---------------------------------------------------------------------------
__device__ __forceinline__ const float* map_src_row(
    int r, const float* __restrict__ E,
    const int* __restrict__ idxp, const int* __restrict__ idxr,
    const int* __restrict__ negp, const int* __restrict__ negr)
{
    if (r < Q_ROWS) {
        int t, local, S;
        if (r < 3600)      { t = 0; local = r;        S = 100; }
        else if (r < 7200) { t = 1; local = r - 3600; S = 100; }
        else if (r < 7920) { t = 2; local = r - 7200; S = 20;  }
        else               { t = 3; local = r - 7920; S = 20;  }
        int perxy = 6 * S;
        int xy  = local / perxy;
        int rem = local - xy * perxy;
        int node = (t < 2) ? idxp[t * 600 + rem] : idxr[(t - 2) * 120 + rem];
        int x = xy / LL, y = xy - x * LL;
        return E + ((size_t)(((t * VV + x) * LL + y) * N_NODES + node)) * D;
    } else {
        int rr = r - Q_ROWS;
        int t, local, K;
        if (rr < 900)       { t = 0; local = rr;        K = 50; }
        else if (rr < 1800) { t = 1; local = rr - 900;  K = 50; }
        else if (rr < 1980) { t = 2; local = rr - 1800; K = 10; }
        else                { t = 3; local = rr - 1980; K = 10; }
        int perO = 6 * K;
        int o   = local / perO;
        int vlk = local - o * perO;
        int vl  = vlk / K;
        int k   = vlk - vl * K;
        int off = (vl * 3 + o) * K + k;
        int node = (t < 2) ? negp[t * 900 + off] : negr[(t - 2) * 180 + off];
        int ot = o + (o >= t ? 1 : 0);
        int v = vl / LL, l = vl - v * LL;
        return E + ((size_t)(((ot * VV + v) * LL + l) * N_NODES + node)) * D;
    }
}

// ---------------------------------------------------------------------------
// store one fp32 float4 -> fp16 uint2 into a W half tile
__device__ __forceinline__ void st_wfrag(char* wdst, int i, float4 v) {
    __half2 p0 = __floats2half2_rn(v.x, v.y);
    __half2 p1 = __floats2half2_rn(v.z, v.w);
    *(uint2*)(wdst + (i >> 5) * WPB + (i & 31) * 8) =
        make_uint2(*reinterpret_cast<unsigned int*>(&p0),
                   *reinterpret_cast<unsigned int*>(&p1));
}

// MMA over one K-half (8 kk steps) while optionally copying the NEXT W half
// (fp32->fp16, one-iteration register pipeline to hide LDG latency).
__device__ __forceinline__ void mma_half(
    uint32_t a_base, uint32_t b_base, float c[2][8][4],
    const float4* __restrict__ wsrc, char* wdst, int tid)
{
    float4 v0, v1;
    if (wsrc) {
        int i0 = tid, i1 = tid + 512;
        v0 = wsrc[(i0 >> 5) * 64 + (i0 & 31)];
        v1 = wsrc[(i1 >> 5) * 64 + (i1 & 31)];
    }
    #pragma unroll
    for (int kk = 0; kk < 8; kk++) {
        if (wsrc) {
            int i0 = kk * 1024 + tid;
            st_wfrag(wdst, i0, v0);
            st_wfrag(wdst, i0 + 512, v1);
            if (kk < 7) {
                int j0 = (kk + 1) * 1024 + tid;
                v0 = wsrc[((j0)       >> 5) * 64 + ((j0)       & 31)];
                v1 = wsrc[((j0 + 512) >> 5) * 64 + ((j0 + 512) & 31)];
            }
        }
        uint32_t a[8];
        ldsm_x4(a,     a_base + kk * 32);
        ldsm_x4(a + 4, a_base + kk * 32 + 16 * APITCH * 2);
        #pragma unroll
        for (int nt = 0; nt < 8; nt++) {
            uint32_t b[2];
            ldsm_x2(b, b_base + kk * 32 + nt * 8 * WPB);
            mma16816(c[0][nt], a,     b);
            mma16816(c[1][nt], a + 4, b);
        }
    }
}

// ---------------------------------------------------------------------------
// Projection: 85 blocks x 512 thr (16 warps: 4 my x 4 cx), 128 rows/block.
// W double-buffered K-halves; copy of next half overlaps MMA of current.
#define SMA   0
#define SMW0  67584                      // A: 128*264*2
#define SMW1  (SMW0 + 256 * WPB)         // 67584 + 69632 = 137216
#define CTRL  (SMW1 + 256 * WPB)         // 206848
#define SM_BYTES (CTRL + 1024 + 1024 + 1024 + 2048)

__global__ void __launch_bounds__(512, 1)
proj_mma_kernel(const float* __restrict__ E,
                const float* __restrict__ W1, const float* __restrict__ b1,
                const float* __restrict__ W2, const float* __restrict__ b2,
                const int* __restrict__ idxp, const int* __restrict__ idxr,
                const int* __restrict__ negp, const int* __restrict__ negr)
{
    extern __shared__ char sm[];
    const uint32_t smb = smem_u32(sm);

    float* smb1 = (float*)(sm + CTRL);
    float* smb2 = (float*)(sm + CTRL + 1024);
    const float** srcp = (const float**)(sm + CTRL + 2048);
    float* ssbuf = (float*)(sm + CTRL + 3072);   // [128][4]

    const int tid = threadIdx.x;
    const int l   = tid & 31;
    const int w   = tid >> 5;
    const int my  = w >> 2;          // 0..3
    const int cx  = w & 3;           // 0..3
    const int r0  = blockIdx.x * ROWS_PB;

    if (blockIdx.x == 0) {
        for (int i = tid; i < N_ANCHORS; i += 512) { g_pos[i] = 0.f; g_neg[i] = 0.f; }
        if (tid == 0) g_ctr = 0u;
    }

    if (tid < 64)        ((float4*)smb1)[tid]      = ((const float4*)b1)[tid];
    else if (tid < 128)  ((float4*)smb2)[tid - 64] = ((const float4*)b2)[tid - 64];
    if (tid < ROWS_PB) {
        int r = r0 + tid;
        srcp[tid] = (r < TOTAL_ROWS)
                  ? map_src_row(r, E, idxp, idxr, negp, negr)
                  : (const float*)0;
    }
    __syncthreads();   // srcp ready

    // W1 half0 copy (upfront) — interleaves with gather LDGs below
    for (int i = tid; i < 8192; i += 512)
        st_wfrag((char*)sm + SMW0, i, ((const float4*)W1)[(i >> 5) * 64 + (i & 31)]);

    // gather X -> fp16 A tile
    for (int i = tid; i < ROWS_PB * 64; i += 512) {
        int m = i >> 6, q = i & 63;
        const float* s = srcp[m];
        float4 v = make_float4(0.f, 0.f, 0.f, 0.f);
        if (s) v = ((const float4*)s)[q];
        __half2 p0 = __floats2half2_rn(v.x, v.y);
        __half2 p1 = __floats2half2_rn(v.z, v.w);
        uint2 pk = make_uint2(*reinterpret_cast<unsigned int*>(&p0),
                              *reinterpret_cast<unsigned int*>(&p1));
        *(uint2*)(sm + SMA + (m * APITCH + q * 4) * 2) = pk;
    }
    __syncthreads();

    const uint32_t a_base = smb + SMA +
        ((my * 32 + ((l >> 3) & 1) * 8 + (l & 7)) * APITCH + (l >> 4) * 8) * 2;
    const uint32_t b_off  = (cx * 64 + (l & 7)) * WPB + ((l >> 3) & 1) * 16;
    const uint32_t b_base0 = smb + SMW0 + b_off;
    const uint32_t b_base1 = smb + SMW1 + b_off;

    const int g  = l >> 2;
    const int q2 = (l & 3) * 2;

    float c[2][8][4];

    // =================== layer 1 ===================
    #pragma unroll
    for (int mt = 0; mt < 2; mt++)
        #pragma unroll
        for (int nt = 0; nt < 8; nt++)
            #pragma unroll
            for (int j = 0; j < 4; j++) c[mt][nt][j] = 0.f;

    // MMA L1h0 (buf0) while copying L1h1 -> buf1
    mma_half(a_base, b_base0, c,
             (const float4*)W1 + 32, (char*)sm + SMW1, tid);
    __syncthreads();
    // MMA L1h1 (buf1) while copying L2h0 -> buf0
    mma_half(a_base + 256, b_base1, c,
             (const float4*)W2, (char*)sm + SMW0, tid);
    __syncthreads();

    // epilogue 1: bias + relu -> fp16 H into A tile
    #pragma unroll
    for (int mt = 0; mt < 2; mt++) {
        #pragma unroll
        for (int nt = 0; nt < 8; nt++) {
            int col = cx * 64 + nt * 8 + q2;
            float bx = smb1[col], by = smb1[col + 1];
            int rlo = my * 32 + mt * 16 + g;
            __half2 lo = __floats2half2_rn(fmaxf(c[mt][nt][0] + bx, 0.f),
                                           fmaxf(c[mt][nt][1] + by, 0.f));
            __half2 hi = __floats2half2_rn(fmaxf(c[mt][nt][2] + bx, 0.f),
                                           fmaxf(c[mt][nt][3] + by, 0.f));
            *(unsigned int*)(sm + SMA + (rlo * APITCH + col) * 2) =
                *reinterpret_cast<unsigned int*>(&lo);
            *(unsigned int*)(sm + SMA + ((rlo + 8) * APITCH + col) * 2) =
                *reinterpret_cast<unsigned int*>(&hi);
        }
    }
    __syncthreads();   // H complete

    // =================== layer 2 ===================
    #pragma unroll
    for (int mt = 0; mt < 2; mt++)
        #pragma unroll
        for (int nt = 0; nt < 8; nt++)
            #pragma unroll
            for (int j = 0; j < 4; j++) c[mt][nt][j] = 0.f;

    // MMA L2h0 (buf0) while copying L2h1 -> buf1
    mma_half(a_base, b_base0, c,
             (const float4*)W2 + 32, (char*)sm + SMW1, tid);
    __syncthreads();
    // MMA L2h1 (buf1), no copy
    mma_half(a_base + 256, b_base1, c, (const float4*)0, (char*)sm, tid);

    // epilogue 2: bias, row L2-norm, fp16 store
    float ss[4] = {0.f, 0.f, 0.f, 0.f};
    #pragma unroll
    for (int mt = 0; mt < 2; mt++) {
        #pragma unroll
        for (int nt = 0; nt < 8; nt++) {
            int col = cx * 64 + nt * 8 + q2;
            float bx = smb2[col], by = smb2[col + 1];
            float z0 = c[mt][nt][0] + bx, z1 = c[mt][nt][1] + by;
            float z2 = c[mt][nt][2] + bx, z3 = c[mt][nt][3] + by;
            ss[mt * 2]     += z0 * z0 + z1 * z1;
            ss[mt * 2 + 1] += z2 * z2 + z3 * z3;
        }
    }
    #pragma unroll
    for (int j = 0; j < 4; j++) {
        ss[j] += __shfl_xor_sync(0xffffffffu, ss[j], 1);
        ss[j] += __shfl_xor_sync(0xffffffffu, ss[j], 2);
    }
    if ((l & 3) == 0) {
        #pragma unroll
        for (int j = 0; j < 4; j++) {
            int row = my * 32 + (j >> 1) * 16 + (j & 1) * 8 + g;
            ssbuf[row * 4 + cx] = ss[j];
        }
    }
    __syncthreads();

    float inv[4];
    #pragma unroll
    for (int j = 0; j < 4; j++) {
        int row = my * 32 + (j >> 1) * 16 + (j & 1) * 8 + g;
        float t = ssbuf[row * 4 + 0] + ssbuf[row * 4 + 1]
                + ssbuf[row * 4 + 2] + ssbuf[row * 4 + 3];
        inv[j] = 1.0f / fmaxf(sqrtf(t), 1e-12f);
    }

    #pragma unroll
    for (int mt = 0; mt < 2; mt++) {
        #pragma unroll
        for (int nt = 0; nt < 8; nt++) {
            int col = cx * 64 + nt * 8 + q2;
            float bx = smb2[col], by = smb2[col + 1];
            int rlo = r0 + my * 32 + mt * 16 + g;
            int rhi = rlo + 8;
            int ci = (col >> 1);
            if (rlo < TOTAL_ROWS) {
                __half2 h = __floats2half2_rn((c[mt][nt][0] + bx) * inv[mt * 2],
                                              (c[mt][nt][1] + by) * inv[mt * 2]);
                g_projh[(size_t)rlo * 128 + ci] = *reinterpret_cast<unsigned int*>(&h);
            }
            if (rhi < TOTAL_ROWS) {
                __half2 h = __floats2half2_rn((c[mt][nt][2] + bx) * inv[mt * 2 + 1],
                                              (c[mt][nt][3] + by) * inv[mt * 2 + 1]);
                g_projh[(size_t)rhi * 128 + ci] = *reinterpret_cast<unsigned int*>(&h);
            }
        }
    }
}

// ---------------------------------------------------------------------------
// Loss (R9 measured-best): 168 blocks x 512 threads, M64 x N128 x K256.
#define LSMA 0
#define LSMB 34816
#define LTRG 102400
#define LSM_BYTES (LTRG + 512 + 512 + 128)

__global__ void __launch_bounds__(512)
loss_mma_kernel(float* __restrict__ out)
{
    extern __shared__ char sm[];
    const uint32_t smb = smem_u32(sm);
    int* targ  = (int*)(sm + LTRG);
    int* tinfo = (int*)(sm + LTRG + 512);

    const int tid = threadIdx.x;
    const int l   = tid & 31;
    const int w   = tid >> 5;
    const int my  = w >> 3;          // 0..1
    const int cx  = w & 7;           // 0..7
    const int b   = blockIdx.x;

    int S, K, vl, chunk, mtile, qbase, pbase, aid0;
    if (b < 144) {
        int t = b / 72, rem = b % 72;
        vl = rem / 12;
        int r2 = rem % 12;
        mtile = r2 / 6; chunk = r2 % 6;
        S = 100; K = 50;
        qbase = t * 3600; pbase = t * 900;
        aid0  = t * 600 + vl * 100;
    } else {
        int bs = b - 144;
        int t2 = bs / 12;
        int rem = bs % 12;
        vl = rem / 2; chunk = rem % 2; mtile = 0;
        S = 20; K = 10;
        qbase = 7200 + t2 * 720; pbase = 1800 + t2 * 180;
        aid0  = 1200 + t2 * 120 + vl * 20;
    }
    const int NTARG = 6 * S + 3 * K;
    const int diag_base = qbase + vl * 7 * S;
    const int mrow0 = mtile * 64;

    if (tid < 128) {
        int n = chunk * 128 + tid;
        int row = 0, info = 0;
        if (n < 6 * S) {
            int xy = n / S, ts = n - xy * S;
            row  = qbase + (xy * 6 + vl) * S + ts;
            info = ts | ((xy == vl) ? 0x10000 : 0) | 0x40000;
        } else if (n < NTARG) {
            int cc = n - 6 * S;
            int o = cc / K, k = cc - o * K;
            row  = Q_ROWS + pbase + (o * 6 + vl) * K + k;
            info = 0x20000 | 0x40000;
        }
        targ[tid]  = row;
        tinfo[tid] = info;
    }
    __syncthreads();

    for (int i = tid; i < 64 * 32; i += 512) {
        int r = i >> 5, q = i & 31;
        int gr = mrow0 + r;
        int arow = diag_base + (gr < S ? gr : 0);
        *(float4*)(sm + LSMA + (r * APITCH + q * 8) * 2) =
            ((const float4*)g_projh)[(size_t)arow * 32 + q];
    }
    for (int i = tid; i < 128 * 32; i += 512) {
        int r = i >> 5, q = i & 31;
        *(float4*)(sm + LSMB + (r * APITCH + q * 8) * 2) =
            ((const float4*)g_projh)[(size_t)targ[r] * 32 + q];
    }
    __syncthreads();

    const uint32_t a_base = smb + LSMA +
        ((my * 32 + ((l >> 3) & 1) * 8 + (l & 7)) * APITCH + (l >> 4) * 8) * 2;
    const uint32_t b_base = smb + LSMB +
        ((cx * 16 + (l & 7)) * APITCH + ((l >> 3) & 1) * 8) * 2;

    float c[2][2][4];
    #pragma unroll
    for (int mt = 0; mt < 2; mt++)
        #pragma unroll
        for (int nt = 0; nt < 2; nt++)
            #pragma unroll
            for (int j = 0; j < 4; j++) c[mt][nt][j] = 0.f;

    #pragma unroll 8
    for (int kk = 0; kk < 16; kk++) {
        uint32_t a[8];
        ldsm_x4(a,     a_base + kk * 32);
        ldsm_x4(a + 4, a_base + kk * 32 + 16 * APITCH * 2);
        #pragma unroll
        for (int nt = 0; nt < 2; nt++) {
            uint32_t bb[2];
            ldsm_x2(bb, b_base + kk * 32 + nt * 8 * APITCH * 2);
            mma16816(c[0][nt], a,     bb);
            mma16816(c[1][nt], a + 4, bb);
        }
    }

    const int g  = l >> 2;
    const int q2 = (l & 3) * 2;
    float pacc[4] = {0.f, 0.f, 0.f, 0.f};
    float nacc[4] = {0.f, 0.f, 0.f, 0.f};

    int rowg[4];
    #pragma unroll
    for (int s = 0; s < 4; s++)
        rowg[s] = mrow0 + my * 32 + (s >> 1) * 16 + (s & 1) * 8 + g;

    #pragma unroll
    for (int nt = 0; nt < 2; nt++) {
        #pragma unroll
        for (int jl = 0; jl < 2; jl++) {
            int info = tinfo[cx * 16 + nt * 8 + q2 + jl];
            if (info & 0x40000) {
                int ts = info & 0xFFFF;
                #pragma unroll
                for (int mt = 0; mt < 2; mt++) {
                    #pragma unroll
                    for (int jh = 0; jh < 2; jh++) {
                        int s = mt * 2 + jh;
                        if (rowg[s] < S) {
                            float e = __expf(2.0f * c[mt][nt][jh * 2 + jl]);
                            if (info & 0x20000)        nacc[s] += e;
                            else if (info & 0x10000) { if (ts != rowg[s]) nacc[s] += e; }
                            else if (ts == rowg[s])    pacc[s] += e;
                        }
                    }
                }
            }
        }
    }

    #pragma unroll
    for (int s = 0; s < 4; s++) {
        pacc[s] += __shfl_xor_sync(0xffffffffu, pacc[s], 1);
        pacc[s] += __shfl_xor_sync(0xffffffffu, pacc[s], 2);
        nacc[s] += __shfl_xor_sync(0xffffffffu, nacc[s], 1);
        nacc[s] += __shfl_xor_sync(0xffffffffu, nacc[s], 2);
    }
    if ((l & 3) == 0) {
        #pragma unroll
        for (int s = 0; s < 4; s++) {
            if (rowg[s] < S) {
                if (pacc[s] != 0.f) atomicAdd(&g_pos[aid0 + rowg[s]], pacc[s]);
                if (nacc[s] != 0.f) atomicAdd(&g_neg[aid0 + rowg[s]], nacc[s]);
            }
        }
    }

    // ---- fused finalize ----
    __shared__ unsigned int is_last;
    __threadfence();
    __syncthreads();
    if (tid == 0)
        is_last = (atomicAdd(&g_ctr, 1u) == (unsigned)(gridDim.x - 1));
    __syncthreads();
    if (is_last) {
        float loc = 0.f;
        for (int i = tid; i < N_ANCHORS; i += 512) {
            float p = g_pos[i], n = g_neg[i];
            loc += -logf(p / (p + n));
        }
        loc += __shfl_xor_sync(0xffffffffu, loc, 16);
        loc += __shfl_xor_sync(0xffffffffu, loc, 8);
        loc += __shfl_xor_sync(0xffffffffu, loc, 4);
        loc += __shfl_xor_sync(0xffffffffu, loc, 2);
        loc += __shfl_xor_sync(0xffffffffu, loc, 1);
        float* red = (float*)(sm + LTRG + 1024);
        if (l == 0) red[w] = loc;
        __syncthreads();
        if (w == 0) {
            float s = (l < 16) ? red[l] : 0.f;
            s += __shfl_xor_sync(0xffffffffu, s, 8);
            s += __shfl_xor_sync(0xffffffffu, s, 4);
            s += __shfl_xor_sync(0xffffffffu, s, 2);
            s += __shfl_xor_sync(0xffffffffu, s, 1);
            if (l == 0) out[0] = s * (1.0f / 1440.0f);
        }
    }
}

// ---------------------------------------------------------------------------
extern "C" void kernel_launch(void* const* d_in, const int* in_sizes, int n_in,
                              void* d_out, int out_size)
{
    const float* E    = (const float*)d_in[0];
    const float* W1   = (const float*)d_in[1];
    const float* b1   = (const float*)d_in[2];
    const float* W2   = (const float*)d_in[3];
    const float* b2   = (const float*)d_in[4];
    const int*   idxp = (const int*)d_in[5];
    const int*   idxr = (const int*)d_in[6];
    const int*   negp = (const int*)d_in[7];
    const int*   negr = (const int*)d_in[8];
    float* out = (float*)d_out;
    (void)in_sizes; (void)n_in; (void)out_size;

    cudaFuncSetAttribute(proj_mma_kernel,
                         cudaFuncAttributeMaxDynamicSharedMemorySize, SM_BYTES);
    cudaFuncSetAttribute(loss_mma_kernel,
                         cudaFuncAttributeMaxDynamicSharedMemorySize, LSM_BYTES);

    proj_mma_kernel<<<PROJ_BLOCKS, 512, SM_BYTES>>>(E, W1, b1, W2, b2,
                                                    idxp, idxr, negp, negr);
    loss_mma_kernel<<<LOSS_BLOCKS, 512, LSM_BYTES>>>(out);
}

// round 13
// speedup vs baseline: 1.0528x; 1.0130x over previous
#include <cuda_runtime.h>
#include <cuda_fp16.h>
#include <math.h>
#include <stdint.h>

// ---------------------------------------------------------------------------
#define D        256
#define N_NODES  4000
#define LL       3
#define VV       2

#define Q_ROWS     8640
#define TOTAL_ROWS 10800
#define N_ANCHORS  1440

#define PROJ_BLOCKS 85      // ceil(10800 / 128)
#define ROWS_PB     128
#define APITCH      264     // tile pitch in halfs (528 B rows)

#define LOSS_BLOCKS 168

__device__ unsigned int g_projh[(size_t)TOTAL_ROWS * 128];  // fp16 proj rows
__device__ float g_pos[N_ANCHORS];
__device__ float g_neg[N_ANCHORS];
__device__ unsigned int g_ctr;

// ---------------------------------------------------------------------------
__device__ __forceinline__ uint32_t smem_u32(const void* p) {
    uint32_t a;
    asm("{ .reg .u64 t; cvta.to.shared.u64 t, %1; cvt.u32.u64 %0, t; }"
        : "=r"(a) : "l"(p));
    return a;
}
__device__ __forceinline__ void ldsm_x4(uint32_t* r, uint32_t addr) {
    asm volatile("ldmatrix.sync.aligned.m8n8.x4.shared.b16 {%0,%1,%2,%3}, [%4];"
                 : "=r"(r[0]), "=r"(r[1]), "=r"(r[2]), "=r"(r[3]) : "r"(addr));
}
__device__ __forceinline__ void mma16816(float* c, const uint32_t* a,
                                         const uint32_t* b) {
    asm volatile("mma.sync.aligned.m16n8k16.row.col.f32.f16.f16.f32 "
                 "{%0,%1,%2,%3}, {%4,%5,%6,%7}, {%8,%9}, {%0,%1,%2,%3};"
                 : "+f"(c[0]), "+f"(c[1]), "+f"(c[2]), "+f"(c[3])
                 : "r"(a[0]), "r"(a[1]), "r"(a[2]), "r"(a[3]),
                   "r"(b[0]), "r"(b[1]));
}

// ---------------------------------------------------------------------------
__device__ __forceinline__ const float* map_src_row(
    int r, const float* __restrict__ E,
    const int* __restrict__ idxp, const int* __restrict__ idxr,
    const int* __restrict__ negp, const int* __restrict__ negr)
{
    if (r < Q_ROWS) {
        int t, local, S;
        if (r < 3600)      { t = 0; local = r;        S = 100; }
        else if (r < 7200) { t = 1; local = r - 3600; S = 100; }
        else if (r < 7920) { t = 2; local = r - 7200; S = 20;  }
        else               { t = 3; local = r - 7920; S = 20;  }
        int perxy = 6 * S;
        int xy  = local / perxy;
        int rem = local - xy * perxy;
        int node = (t < 2) ? idxp[t * 600 + rem] : idxr[(t - 2) * 120 + rem];
        int x = xy / LL, y = xy - x * LL;
        return E + ((size_t)(((t * VV + x) * LL + y) * N_NODES + node)) * D;
    } else {
        int rr = r - Q_ROWS;
        int t, local, K;
        if (rr < 900)       { t = 0; local = rr;        K = 50; }
        else if (rr < 1800) { t = 1; local = rr - 900;  K = 50; }
        else if (rr < 1980) { t = 2; local = rr - 1800; K = 10; }
        else                { t = 3; local = rr - 1980; K = 10; }
        int perO = 6 * K;
        int o   = local / perO;
        int vlk = local - o * perO;
        int vl  = vlk / K;
        int k   = vlk - vl * K;
        int off = (vl * 3 + o) * K + k;
        int node = (t < 2) ? negp[t * 900 + off] : negr[(t - 2) * 180 + off];
        int ot = o + (o >= t ? 1 : 0);
        int v = vl / LL, l = vl - v * LL;
        return E + ((size_t)(((ot * VV + v) * LL + l) * N_NODES + node)) * D;
    }
}

// ---------------------------------------------------------------------------
// Projection: 85 blocks x 512 thr (16 warps: 4 my x 4 cx), full-W smem,
// B fragments loaded with ldmatrix.x4 (two n-tiles per load).
#define SMA   0
#define SMW   67584
#define CTRL  202752
#define SM_BYTES (CTRL + 3072 + 2048)

__global__ void __launch_bounds__(512, 1)
proj_mma_kernel(const float* __restrict__ E,
                const float* __restrict__ W1, const float* __restrict__ b1,
                const float* __restrict__ W2, const float* __restrict__ b2,
                const int* __restrict__ idxp, const int* __restrict__ idxr,
                const int* __restrict__ negp, const int* __restrict__ negr)
{
    extern __shared__ char sm[];
    const uint32_t smb = smem_u32(sm);

    float* smb1 = (float*)(sm + CTRL);
    float* smb2 = (float*)(sm + CTRL + 1024);
    const float** srcp = (const float**)(sm + CTRL + 2048);
    float* ssbuf = (float*)(sm + CTRL + 3072);   // [128][4]

    const int tid = threadIdx.x;
    const int l   = tid & 31;
    const int w   = tid >> 5;
    const int my  = w >> 2;          // 0..3
    const int cx  = w & 3;           // 0..3
    const int r0  = blockIdx.x * ROWS_PB;

    if (blockIdx.x == 0) {
        for (int i = tid; i < N_ANCHORS; i += 512) { g_pos[i] = 0.f; g_neg[i] = 0.f; }
        if (tid == 0) g_ctr = 0u;
    }

    if (tid < 64)        ((float4*)smb1)[tid]      = ((const float4*)b1)[tid];
    else if (tid < 128)  ((float4*)smb2)[tid - 64] = ((const float4*)b2)[tid - 64];
    if (tid < ROWS_PB) {
        int r = r0 + tid;
        srcp[tid] = (r < TOTAL_ROWS)
                  ? map_src_row(r, E, idxp, idxr, negp, negr)
                  : (const float*)0;
    }

    // W1 fp32 -> fp16 smem tile
    for (int i = tid; i < 16384; i += 512) {
        int n = i >> 6, q = i & 63;
        float4 v = ((const float4*)W1)[i];
        __half2 p0 = __floats2half2_rn(v.x, v.y);
        __half2 p1 = __floats2half2_rn(v.z, v.w);
        uint2 pk = make_uint2(*reinterpret_cast<unsigned int*>(&p0),
                              *reinterpret_cast<unsigned int*>(&p1));
        *(uint2*)(sm + SMW + (n * APITCH + q * 4) * 2) = pk;
    }
    __syncthreads();

    // gather X -> fp16 A tile
    for (int i = tid; i < ROWS_PB * 64; i += 512) {
        int m = i >> 6, q = i & 63;
        const float* s = srcp[m];
        float4 v = make_float4(0.f, 0.f, 0.f, 0.f);
        if (s) v = ((const float4*)s)[q];
        __half2 p0 = __floats2half2_rn(v.x, v.y);
        __half2 p1 = __floats2half2_rn(v.z, v.w);
        uint2 pk = make_uint2(*reinterpret_cast<unsigned int*>(&p0),
                              *reinterpret_cast<unsigned int*>(&p1));
        *(uint2*)(sm + SMA + (m * APITCH + q * 4) * 2) = pk;
    }
    __syncthreads();

    const uint32_t a_base = smb + SMA +
        ((my * 32 + ((l >> 3) & 1) * 8 + (l & 7)) * APITCH + (l >> 4) * 8) * 2;
    // x4 B base: lanes 16-31 address rows n+8..15 (matrices 2,3)
    const uint32_t b_base = smb + SMW +
        ((cx * 64 + ((l >> 4) & 1) * 8 + (l & 7)) * APITCH + ((l >> 3) & 1) * 8) * 2;

    float c[2][8][4];

    // layer 1
    #pragma unroll
    for (int mt = 0; mt < 2; mt++)
        #pragma unroll
        for (int nt = 0; nt < 8; nt++)
            #pragma unroll
            for (int j = 0; j < 4; j++) c[mt][nt][j] = 0.f;

    #pragma unroll 4
    for (int kk = 0; kk < 16; kk++) {
        uint32_t a[8];
        ldsm_x4(a,     a_base + kk * 32);
        ldsm_x4(a + 4, a_base + kk * 32 + 16 * APITCH * 2);
        #pragma unroll
        for (int ntp = 0; ntp < 4; ntp++) {
            uint32_t b4[4];
            ldsm_x4(b4, b_base + kk * 32 + ntp * 16 * APITCH * 2);
            mma16816(c[0][2*ntp],   a,     b4);
            mma16816(c[1][2*ntp],   a + 4, b4);
            mma16816(c[0][2*ntp+1], a,     b4 + 2);
            mma16816(c[1][2*ntp+1], a + 4, b4 + 2);
        }
    }
    __syncthreads();

    const int g  = l >> 2;
    const int q2 = (l & 3) * 2;
    #pragma unroll
    for (int mt = 0; mt < 2; mt++) {
        #pragma unroll
        for (int nt = 0; nt < 8; nt++) {
            int col = cx * 64 + nt * 8 + q2;
            float bx = smb1[col], by = smb1[col + 1];
            int rlo = my * 32 + mt * 16 + g;
            __half2 lo = __floats2half2_rn(fmaxf(c[mt][nt][0] + bx, 0.f),
                                           fmaxf(c[mt][nt][1] + by, 0.f));
            __half2 hi = __floats2half2_rn(fmaxf(c[mt][nt][2] + bx, 0.f),
                                           fmaxf(c[mt][nt][3] + by, 0.f));
            *(unsigned int*)(sm + SMA + (rlo * APITCH + col) * 2) =
                *reinterpret_cast<unsigned int*>(&lo);
            *(unsigned int*)(sm + SMA + ((rlo + 8) * APITCH + col) * 2) =
                *reinterpret_cast<unsigned int*>(&hi);
        }
    }
    // W2 fp32 -> fp16 smem tile
    for (int i = tid; i < 16384; i += 512) {
        int n = i >> 6, q = i & 63;
        float4 v = ((const float4*)W2)[i];
        __half2 p0 = __floats2half2_rn(v.x, v.y);
        __half2 p1 = __floats2half2_rn(v.z, v.w);
        uint2 pk = make_uint2(*reinterpret_cast<unsigned int*>(&p0),
                              *reinterpret_cast<unsigned int*>(&p1));
        *(uint2*)(sm + SMW + (n * APITCH + q * 4) * 2) = pk;
    }
    __syncthreads();

    // layer 2
    #pragma unroll
    for (int mt = 0; mt < 2; mt++)
        #pragma unroll
        for (int nt = 0; nt < 8; nt++)
            #pragma unroll
            for (int j = 0; j < 4; j++) c[mt][nt][j] = 0.f;

    #pragma unroll 4
    for (int kk = 0; kk < 16; kk++) {
        uint32_t a[8];
        ldsm_x4(a,     a_base + kk * 32);
        ldsm_x4(a + 4, a_base + kk * 32 + 16 * APITCH * 2);
        #pragma unroll
        for (int ntp = 0; ntp < 4; ntp++) {
            uint32_t b4[4];
            ldsm_x4(b4, b_base + kk * 32 + ntp * 16 * APITCH * 2);
            mma16816(c[0][2*ntp],   a,     b4);
            mma16816(c[1][2*ntp],   a + 4, b4);
            mma16816(c[0][2*ntp+1], a,     b4 + 2);
            mma16816(c[1][2*ntp+1], a + 4, b4 + 2);
        }
    }

    // epilogue: bias, row L2-norm, fp16 store
    float ss[4] = {0.f, 0.f, 0.f, 0.f};
    #pragma unroll
    for (int mt = 0; mt < 2; mt++) {
        #pragma unroll
        for (int nt = 0; nt < 8; nt++) {
            int col = cx * 64 + nt * 8 + q2;
            float bx = smb2[col], by = smb2[col + 1];
            float z0 = c[mt][nt][0] + bx, z1 = c[mt][nt][1] + by;
            float z2 = c[mt][nt][2] + bx, z3 = c[mt][nt][3] + by;
            ss[mt * 2]     += z0 * z0 + z1 * z1;
            ss[mt * 2 + 1] += z2 * z2 + z3 * z3;
        }
    }
    #pragma unroll
    for (int j = 0; j < 4; j++) {
        ss[j] += __shfl_xor_sync(0xffffffffu, ss[j], 1);
        ss[j] += __shfl_xor_sync(0xffffffffu, ss[j], 2);
    }
    if ((l & 3) == 0) {
        #pragma unroll
        for (int j = 0; j < 4; j++) {
            int row = my * 32 + (j >> 1) * 16 + (j & 1) * 8 + g;
            ssbuf[row * 4 + cx] = ss[j];
        }
    }
    __syncthreads();

    float inv[4];
    #pragma unroll
    for (int j = 0; j < 4; j++) {
        int row = my * 32 + (j >> 1) * 16 + (j & 1) * 8 + g;
        float t = ssbuf[row * 4 + 0] + ssbuf[row * 4 + 1]
                + ssbuf[row * 4 + 2] + ssbuf[row * 4 + 3];
        inv[j] = 1.0f / fmaxf(sqrtf(t), 1e-12f);
    }

    #pragma unroll
    for (int mt = 0; mt < 2; mt++) {
        #pragma unroll
        for (int nt = 0; nt < 8; nt++) {
            int col = cx * 64 + nt * 8 + q2;
            float bx = smb2[col], by = smb2[col + 1];
            int rlo = r0 + my * 32 + mt * 16 + g;
            int rhi = rlo + 8;
            int ci = (col >> 1);
            if (rlo < TOTAL_ROWS) {
                __half2 h = __floats2half2_rn((c[mt][nt][0] + bx) * inv[mt * 2],
                                              (c[mt][nt][1] + by) * inv[mt * 2]);
                g_projh[(size_t)rlo * 128 + ci] = *reinterpret_cast<unsigned int*>(&h);
            }
            if (rhi < TOTAL_ROWS) {
                __half2 h = __floats2half2_rn((c[mt][nt][2] + bx) * inv[mt * 2 + 1],
                                              (c[mt][nt][3] + by) * inv[mt * 2 + 1]);
                g_projh[(size_t)rhi * 128 + ci] = *reinterpret_cast<unsigned int*>(&h);
            }
        }
    }
}

// ---------------------------------------------------------------------------
// Loss: 168 blocks x 512 threads, M64 x N128 x K256; B via ldmatrix.x4.
#define LSMA 0
#define LSMB 34816
#define LTRG 102400
#define LSM_BYTES (LTRG + 512 + 512 + 128)

__global__ void __launch_bounds__(512)
loss_mma_kernel(float* __restrict__ out)
{
    extern __shared__ char sm[];
    const uint32_t smb = smem_u32(sm);
    int* targ  = (int*)(sm + LTRG);
    int* tinfo = (int*)(sm + LTRG + 512);

    const int tid = threadIdx.x;
    const int l   = tid & 31;
    const int w   = tid >> 5;
    const int my  = w >> 3;          // 0..1
    const int cx  = w & 7;           // 0..7
    const int b   = blockIdx.x;

    int S, K, vl, chunk, mtile, qbase, pbase, aid0;
    if (b < 144) {
        int t = b / 72, rem = b % 72;
        vl = rem / 12;
        int r2 = rem % 12;
        mtile = r2 / 6; chunk = r2 % 6;
        S = 100; K = 50;
        qbase = t * 3600; pbase = t * 900;
        aid0  = t * 600 + vl * 100;
    } else {
        int bs = b - 144;
        int t2 = bs / 12;
        int rem = bs % 12;
        vl = rem / 2; chunk = rem % 2; mtile = 0;
        S = 20; K = 10;
        qbase = 7200 + t2 * 720; pbase = 1800 + t2 * 180;
        aid0  = 1200 + t2 * 120 + vl * 20;
    }
    const int NTARG = 6 * S + 3 * K;
    const int diag_base = qbase + vl * 7 * S;
    const int mrow0 = mtile * 64;

    if (tid < 128) {
        int n = chunk * 128 + tid;
        int row = 0, info = 0;
        if (n < 6 * S) {
            int xy = n / S, ts = n - xy * S;
            row  = qbase + (xy * 6 + vl) * S + ts;
            info = ts | ((xy == vl) ? 0x10000 : 0) | 0x40000;
        } else if (n < NTARG) {
            int cc = n - 6 * S;
            int o = cc / K, k = cc - o * K;
            row  = Q_ROWS + pbase + (o * 6 + vl) * K + k;
            info = 0x20000 | 0x40000;
        }
        targ[tid]  = row;
        tinfo[tid] = info;
    }
    __syncthreads();

    for (int i = tid; i < 64 * 32; i += 512) {
        int r = i >> 5, q = i & 31;
        int gr = mrow0 + r;
        int arow = diag_base + (gr < S ? gr : 0);
        *(float4*)(sm + LSMA + (r * APITCH + q * 8) * 2) =
            ((const float4*)g_projh)[(size_t)arow * 32 + q];
    }
    for (int i = tid; i < 128 * 32; i += 512) {
        int r = i >> 5, q = i & 31;
        *(float4*)(sm + LSMB + (r * APITCH + q * 8) * 2) =
            ((const float4*)g_projh)[(size_t)targ[r] * 32 + q];
    }
    __syncthreads();

    const uint32_t a_base = smb + LSMA +
        ((my * 32 + ((l >> 3) & 1) * 8 + (l & 7)) * APITCH + (l >> 4) * 8) * 2;
    // x4 B base: two n-tiles per load
    const uint32_t b_base = smb + LSMB +
        ((cx * 16 + ((l >> 4) & 1) * 8 + (l & 7)) * APITCH + ((l >> 3) & 1) * 8) * 2;

    float c[2][2][4];
    #pragma unroll
    for (int mt = 0; mt < 2; mt++)
        #pragma unroll
        for (int nt = 0; nt < 2; nt++)
            #pragma unroll
            for (int j = 0; j < 4; j++) c[mt][nt][j] = 0.f;

    #pragma unroll 8
    for (int kk = 0; kk < 16; kk++) {
        uint32_t a[8];
        ldsm_x4(a,     a_base + kk * 32);
        ldsm_x4(a + 4, a_base + kk * 32 + 16 * APITCH * 2);
        uint32_t b4[4];
        ldsm_x4(b4, b_base + kk * 32);
        mma16816(c[0][0], a,     b4);
        mma16816(c[1][0], a + 4, b4);
        mma16816(c[0][1], a,     b4 + 2);
        mma16816(c[1][1], a + 4, b4 + 2);
    }

    const int g  = l >> 2;
    const int q2 = (l & 3) * 2;
    float pacc[4] = {0.f, 0.f, 0.f, 0.f};
    float nacc[4] = {0.f, 0.f, 0.f, 0.f};

    int rowg[4];
    #pragma unroll
    for (int s = 0; s < 4; s++)
        rowg[s] = mrow0 + my * 32 + (s >> 1) * 16 + (s & 1) * 8 + g;

    #pragma unroll
    for (int nt = 0; nt < 2; nt++) {
        #pragma unroll
        for (int jl = 0; jl < 2; jl++) {
            int info = tinfo[cx * 16 + nt * 8 + q2 + jl];
            if (info & 0x40000) {
                int ts = info & 0xFFFF;
                #pragma unroll
                for (int mt = 0; mt < 2; mt++) {
                    #pragma unroll
                    for (int jh = 0; jh < 2; jh++) {
                        int s = mt * 2 + jh;
                        if (rowg[s] < S) {
                            float e = __expf(2.0f * c[mt][nt][jh * 2 + jl]);
                            if (info & 0x20000)        nacc[s] += e;
                            else if (info & 0x10000) { if (ts != rowg[s]) nacc[s] += e; }
                            else if (ts == rowg[s])    pacc[s] += e;
                        }
                    }
                }
            }
        }
    }

    #pragma unroll
    for (int s = 0; s < 4; s++) {
        pacc[s] += __shfl_xor_sync(0xffffffffu, pacc[s], 1);
        pacc[s] += __shfl_xor_sync(0xffffffffu, pacc[s], 2);
        nacc[s] += __shfl_xor_sync(0xffffffffu, nacc[s], 1);
        nacc[s] += __shfl_xor_sync(0xffffffffu, nacc[s], 2);
    }
    if ((l & 3) == 0) {
        #pragma unroll
        for (int s = 0; s < 4; s++) {
            if (rowg[s] < S) {
                if (pacc[s] != 0.f) atomicAdd(&g_pos[aid0 + rowg[s]], pacc[s]);
                if (nacc[s] != 0.f) atomicAdd(&g_neg[aid0 + rowg[s]], nacc[s]);
            }
        }
    }

    // ---- fused finalize ----
    __shared__ unsigned int is_last;
    __threadfence();
    __syncthreads();
    if (tid == 0)
        is_last = (atomicAdd(&g_ctr, 1u) == (unsigned)(gridDim.x - 1));
    __syncthreads();
    if (is_last) {
        float loc = 0.f;
        for (int i = tid; i < N_ANCHORS; i += 512) {
            float p = g_pos[i], n = g_neg[i];
            loc += -logf(p / (p + n));
        }
        loc += __shfl_xor_sync(0xffffffffu, loc, 16);
        loc += __shfl_xor_sync(0xffffffffu, loc, 8);
        loc += __shfl_xor_sync(0xffffffffu, loc, 4);
        loc += __shfl_xor_sync(0xffffffffu, loc, 2);
        loc += __shfl_xor_sync(0xffffffffu, loc, 1);
        float* red = (float*)(sm + LTRG + 1024);
        if (l == 0) red[w] = loc;
        __syncthreads();
        if (w == 0) {
            float s = (l < 16) ? red[l] : 0.f;
            s += __shfl_xor_sync(0xffffffffu, s, 8);
            s += __shfl_xor_sync(0xffffffffu, s, 4);
            s += __shfl_xor_sync(0xffffffffu, s, 2);
            s += __shfl_xor_sync(0xffffffffu, s, 1);
            if (l == 0) out[0] = s * (1.0f / 1440.0f);
        }
    }
}

// ---------------------------------------------------------------------------
extern "C" void kernel_launch(void* const* d_in, const int* in_sizes, int n_in,
                              void* d_out, int out_size)
{
    const float* E    = (const float*)d_in[0];
    const float* W1   = (const float*)d_in[1];
    const float* b1   = (const float*)d_in[2];
    const float* W2   = (const float*)d_in[3];
    const float* b2   = (const float*)d_in[4];
    const int*   idxp = (const int*)d_in[5];
    const int*   idxr = (const int*)d_in[6];
    const int*   negp = (const int*)d_in[7];
    const int*   negr = (const int*)d_in[8];
    float* out = (float*)d_out;
    (void)in_sizes; (void)n_in; (void)out_size;

    cudaFuncSetAttribute(proj_mma_kernel,
                         cudaFuncAttributeMaxDynamicSharedMemorySize, SM_BYTES);
    cudaFuncSetAttribute(loss_mma_kernel,
                         cudaFuncAttributeMaxDynamicSharedMemorySize, LSM_BYTES);

    proj_mma_kernel<<<PROJ_BLOCKS, 512, SM_BYTES>>>(E, W1, b1, W2, b2,
                                                    idxp, idxr, negp, negr);
    loss_mma_kernel<<<LOSS_BLOCKS, 512, LSM_BYTES>>>(out);
}

// round 14
// speedup vs baseline: 1.0640x; 1.0107x over previous
#include <cuda_runtime.h>
#include <cuda_fp16.h>
#include <cuda_fp8.h>
#include <math.h>
#include <stdint.h>

// ---------------------------------------------------------------------------
#define D        256
#define N_NODES  4000
#define LL       3
#define VV       2

#define Q_ROWS     8640
#define TOTAL_ROWS 10800
#define N_ANCHORS  1440

#define PROJ_BLOCKS 85      // ceil(10800 / 128)
#define ROWS_PB     128
#define APITCH      264     // fp16 tile pitch in halfs (528 B rows)
#define FPITCH      272     // fp8 tile pitch in bytes (256B data + 16 pad)

#define LOSS_BLOCKS 168

__device__ unsigned short g_proj8[(size_t)TOTAL_ROWS * 128];  // e4m3x2 proj rows
__device__ float g_pos[N_ANCHORS];
__device__ float g_neg[N_ANCHORS];
__device__ unsigned int g_ctr;

// ---------------------------------------------------------------------------
__device__ __forceinline__ uint32_t smem_u32(const void* p) {
    uint32_t a;
    asm("{ .reg .u64 t; cvta.to.shared.u64 t, %1; cvt.u32.u64 %0, t; }"
        : "=r"(a) : "l"(p));
    return a;
}
__device__ __forceinline__ void ldsm_x4(uint32_t* r, uint32_t addr) {
    asm volatile("ldmatrix.sync.aligned.m8n8.x4.shared.b16 {%0,%1,%2,%3}, [%4];"
                 : "=r"(r[0]), "=r"(r[1]), "=r"(r[2]), "=r"(r[3]) : "r"(addr));
}
__device__ __forceinline__ void mma16816(float* c, const uint32_t* a,
                                         const uint32_t* b) {
    asm volatile("mma.sync.aligned.m16n8k16.row.col.f32.f16.f16.f32 "
                 "{%0,%1,%2,%3}, {%4,%5,%6,%7}, {%8,%9}, {%0,%1,%2,%3};"
                 : "+f"(c[0]), "+f"(c[1]), "+f"(c[2]), "+f"(c[3])
                 : "r"(a[0]), "r"(a[1]), "r"(a[2]), "r"(a[3]),
                   "r"(b[0]), "r"(b[1]));
}
__device__ __forceinline__ void mma16832fp8(float* c, const uint32_t* a,
                                            const uint32_t* b) {
    asm volatile("mma.sync.aligned.m16n8k32.row.col.f32.e4m3.e4m3.f32 "
                 "{%0,%1,%2,%3}, {%4,%5,%6,%7}, {%8,%9}, {%0,%1,%2,%3};"
                 : "+f"(c[0]), "+f"(c[1]), "+f"(c[2]), "+f"(c[3])
                 : "r"(a[0]), "r"(a[1]), "r"(a[2]), "r"(a[3]),
                   "r"(b[0]), "r"(b[1]));
}
__device__ __forceinline__ unsigned short pack_e4m3x2(float x, float y) {
    __nv_fp8x2_e4m3 f8(make_float2(x, y));
    return *reinterpret_cast<unsigned short*>(&f8);
}

// ---------------------------------------------------------------------------
__device__ __forceinline__ const float* map_src_row(
    int r, const float* __restrict__ E,
    const int* __restrict__ idxp, const int* __restrict__ idxr,
    const int* __restrict__ negp, const int* __restrict__ negr)
{
    if (r < Q_ROWS) {
        int t, local, S;
        if (r < 3600)      { t = 0; local = r;        S = 100; }
        else if (r < 7200) { t = 1; local = r - 3600; S = 100; }
        else if (r < 7920) { t = 2; local = r - 7200; S = 20;  }
        else               { t = 3; local = r - 7920; S = 20;  }
        int perxy = 6 * S;
        int xy  = local / perxy;
        int rem = local - xy * perxy;
        int node = (t < 2) ? idxp[t * 600 + rem] : idxr[(t - 2) * 120 + rem];
        int x = xy / LL, y = xy - x * LL;
        return E + ((size_t)(((t * VV + x) * LL + y) * N_NODES + node)) * D;
    } else {
        int rr = r - Q_ROWS;
        int t, local, K;
        if (rr < 900)       { t = 0; local = rr;        K = 50; }
        else if (rr < 1800) { t = 1; local = rr - 900;  K = 50; }
        else if (rr < 1980) { t = 2; local = rr - 1800; K = 10; }
        else                { t = 3; local = rr - 1980; K = 10; }
        int perO = 6 * K;
        int o   = local / perO;
        int vlk = local - o * perO;
        int vl  = vlk / K;
        int k   = vlk - vl * K;
        int off = (vl * 3 + o) * K + k;
        int node = (t < 2) ? negp[t * 900 + off] : negr[(t - 2) * 180 + off];
        int ot = o + (o >= t ? 1 : 0);
        int v = vl / LL, l = vl - v * LL;
        return E + ((size_t)(((ot * VV + v) * LL + l) * N_NODES + node)) * D;
    }
}

// ---------------------------------------------------------------------------
// Projection: 85 blocks x 512 thr (16 warps: 4 my x 4 cx), fp16 HMMA,
// x4 B-fragment loads; epilogue writes e4m3 rows.
#define SMA   0
#define SMW   67584
#define CTRL  202752
#define SM_BYTES (CTRL + 3072 + 2048)

__global__ void __launch_bounds__(512, 1)
proj_mma_kernel(const float* __restrict__ E,
                const float* __restrict__ W1, const float* __restrict__ b1,
                const float* __restrict__ W2, const float* __restrict__ b2,
                const int* __restrict__ idxp, const int* __restrict__ idxr,
                const int* __restrict__ negp, const int* __restrict__ negr)
{
    extern __shared__ char sm[];
    const uint32_t smb = smem_u32(sm);

    float* smb1 = (float*)(sm + CTRL);
    float* smb2 = (float*)(sm + CTRL + 1024);
    const float** srcp = (const float**)(sm + CTRL + 2048);
    float* ssbuf = (float*)(sm + CTRL + 3072);   // [128][4]

    const int tid = threadIdx.x;
    const int l   = tid & 31;
    const int w   = tid >> 5;
    const int my  = w >> 2;          // 0..3
    const int cx  = w & 3;           // 0..3
    const int r0  = blockIdx.x * ROWS_PB;

    if (blockIdx.x == 0) {
        for (int i = tid; i < N_ANCHORS; i += 512) { g_pos[i] = 0.f; g_neg[i] = 0.f; }
        if (tid == 0) g_ctr = 0u;
    }

    if (tid < 64)        ((float4*)smb1)[tid]      = ((const float4*)b1)[tid];
    else if (tid < 128)  ((float4*)smb2)[tid - 64] = ((const float4*)b2)[tid - 64];
    if (tid < ROWS_PB) {
        int r = r0 + tid;
        srcp[tid] = (r < TOTAL_ROWS)
                  ? map_src_row(r, E, idxp, idxr, negp, negr)
                  : (const float*)0;
    }

    // W1 fp32 -> fp16 smem tile
    for (int i = tid; i < 16384; i += 512) {
        int n = i >> 6, q = i & 63;
        float4 v = ((const float4*)W1)[i];
        __half2 p0 = __floats2half2_rn(v.x, v.y);
        __half2 p1 = __floats2half2_rn(v.z, v.w);
        uint2 pk = make_uint2(*reinterpret_cast<unsigned int*>(&p0),
                              *reinterpret_cast<unsigned int*>(&p1));
        *(uint2*)(sm + SMW + (n * APITCH + q * 4) * 2) = pk;
    }
    __syncthreads();

    // gather X -> fp16 A tile
    for (int i = tid; i < ROWS_PB * 64; i += 512) {
        int m = i >> 6, q = i & 63;
        const float* s = srcp[m];
        float4 v = make_float4(0.f, 0.f, 0.f, 0.f);
        if (s) v = ((const float4*)s)[q];
        __half2 p0 = __floats2half2_rn(v.x, v.y);
        __half2 p1 = __floats2half2_rn(v.z, v.w);
        uint2 pk = make_uint2(*reinterpret_cast<unsigned int*>(&p0),
                              *reinterpret_cast<unsigned int*>(&p1));
        *(uint2*)(sm + SMA + (m * APITCH + q * 4) * 2) = pk;
    }
    __syncthreads();

    const uint32_t a_base = smb + SMA +
        ((my * 32 + ((l >> 3) & 1) * 8 + (l & 7)) * APITCH + (l >> 4) * 8) * 2;
    const uint32_t b_base = smb + SMW +
        ((cx * 64 + ((l >> 4) & 1) * 8 + (l & 7)) * APITCH + ((l >> 3) & 1) * 8) * 2;

    float c[2][8][4];

    // layer 1
    #pragma unroll
    for (int mt = 0; mt < 2; mt++)
        #pragma unroll
        for (int nt = 0; nt < 8; nt++)
            #pragma unroll
            for (int j = 0; j < 4; j++) c[mt][nt][j] = 0.f;

    #pragma unroll 4
    for (int kk = 0; kk < 16; kk++) {
        uint32_t a[8];
        ldsm_x4(a,     a_base + kk * 32);
        ldsm_x4(a + 4, a_base + kk * 32 + 16 * APITCH * 2);
        #pragma unroll
        for (int ntp = 0; ntp < 4; ntp++) {
            uint32_t b4[4];
            ldsm_x4(b4, b_base + kk * 32 + ntp * 16 * APITCH * 2);
            mma16816(c[0][2*ntp],   a,     b4);
            mma16816(c[1][2*ntp],   a + 4, b4);
            mma16816(c[0][2*ntp+1], a,     b4 + 2);
            mma16816(c[1][2*ntp+1], a + 4, b4 + 2);
        }
    }
    __syncthreads();

    const int g  = l >> 2;
    const int q2 = (l & 3) * 2;
    #pragma unroll
    for (int mt = 0; mt < 2; mt++) {
        #pragma unroll
        for (int nt = 0; nt < 8; nt++) {
            int col = cx * 64 + nt * 8 + q2;
            float bx = smb1[col], by = smb1[col + 1];
            int rlo = my * 32 + mt * 16 + g;
            __half2 lo = __floats2half2_rn(fmaxf(c[mt][nt][0] + bx, 0.f),
                                           fmaxf(c[mt][nt][1] + by, 0.f));
            __half2 hi = __floats2half2_rn(fmaxf(c[mt][nt][2] + bx, 0.f),
                                           fmaxf(c[mt][nt][3] + by, 0.f));
            *(unsigned int*)(sm + SMA + (rlo * APITCH + col) * 2) =
                *reinterpret_cast<unsigned int*>(&lo);
            *(unsigned int*)(sm + SMA + ((rlo + 8) * APITCH + col) * 2) =
                *reinterpret_cast<unsigned int*>(&hi);
        }
    }
    // W2 fp32 -> fp16 smem tile
    for (int i = tid; i < 16384; i += 512) {
        int n = i >> 6, q = i & 63;
        float4 v = ((const float4*)W2)[i];
        __half2 p0 = __floats2half2_rn(v.x, v.y);
        __half2 p1 = __floats2half2_rn(v.z, v.w);
        uint2 pk = make_uint2(*reinterpret_cast<unsigned int*>(&p0),
                              *reinterpret_cast<unsigned int*>(&p1));
        *(uint2*)(sm + SMW + (n * APITCH + q * 4) * 2) = pk;
    }
    __syncthreads();

    // layer 2
    #pragma unroll
    for (int mt = 0; mt < 2; mt++)
        #pragma unroll
        for (int nt = 0; nt < 8; nt++)
            #pragma unroll
            for (int j = 0; j < 4; j++) c[mt][nt][j] = 0.f;

    #pragma unroll 4
    for (int kk = 0; kk < 16; kk++) {
        uint32_t a[8];
        ldsm_x4(a,     a_base + kk * 32);
        ldsm_x4(a + 4, a_base + kk * 32 + 16 * APITCH * 2);
        #pragma unroll
        for (int ntp = 0; ntp < 4; ntp++) {
            uint32_t b4[4];
            ldsm_x4(b4, b_base + kk * 32 + ntp * 16 * APITCH * 2);
            mma16816(c[0][2*ntp],   a,     b4);
            mma16816(c[1][2*ntp],   a + 4, b4);
            mma16816(c[0][2*ntp+1], a,     b4 + 2);
            mma16816(c[1][2*ntp+1], a + 4, b4 + 2);
        }
    }

    // epilogue: bias, row L2-norm, e4m3 store
    float ss[4] = {0.f, 0.f, 0.f, 0.f};
    #pragma unroll
    for (int mt = 0; mt < 2; mt++) {
        #pragma unroll
        for (int nt = 0; nt < 8; nt++) {
            int col = cx * 64 + nt * 8 + q2;
            float bx = smb2[col], by = smb2[col + 1];
            float z0 = c[mt][nt][0] + bx, z1 = c[mt][nt][1] + by;
            float z2 = c[mt][nt][2] + bx, z3 = c[mt][nt][3] + by;
            ss[mt * 2]     += z0 * z0 + z1 * z1;
            ss[mt * 2 + 1] += z2 * z2 + z3 * z3;
        }
    }
    #pragma unroll
    for (int j = 0; j < 4; j++) {
        ss[j] += __shfl_xor_sync(0xffffffffu, ss[j], 1);
        ss[j] += __shfl_xor_sync(0xffffffffu, ss[j], 2);
    }
    if ((l & 3) == 0) {
        #pragma unroll
        for (int j = 0; j < 4; j++) {
            int row = my * 32 + (j >> 1) * 16 + (j & 1) * 8 + g;
            ssbuf[row * 4 + cx] = ss[j];
        }
    }
    __syncthreads();

    float inv[4];
    #pragma unroll
    for (int j = 0; j < 4; j++) {
        int row = my * 32 + (j >> 1) * 16 + (j & 1) * 8 + g;
        float t = ssbuf[row * 4 + 0] + ssbuf[row * 4 + 1]
                + ssbuf[row * 4 + 2] + ssbuf[row * 4 + 3];
        inv[j] = 1.0f / fmaxf(sqrtf(t), 1e-12f);
    }

    #pragma unroll
    for (int mt = 0; mt < 2; mt++) {
        #pragma unroll
        for (int nt = 0; nt < 8; nt++) {
            int col = cx * 64 + nt * 8 + q2;
            float bx = smb2[col], by = smb2[col + 1];
            int rlo = r0 + my * 32 + mt * 16 + g;
            int rhi = rlo + 8;
            int ci = (col >> 1);
            if (rlo < TOTAL_ROWS)
                g_proj8[(size_t)rlo * 128 + ci] =
                    pack_e4m3x2((c[mt][nt][0] + bx) * inv[mt * 2],
                                (c[mt][nt][1] + by) * inv[mt * 2]);
            if (rhi < TOTAL_ROWS)
                g_proj8[(size_t)rhi * 128 + ci] =
                    pack_e4m3x2((c[mt][nt][2] + bx) * inv[mt * 2 + 1],
                                (c[mt][nt][3] + by) * inv[mt * 2 + 1]);
        }
    }
}

// ---------------------------------------------------------------------------
// Loss: 168 blocks x 512 threads, M64 x N128 x K256 in e4m3 (m16n8k32).
// fp8 tiles: 272-byte pitch; ldmatrix addressing identical to fp16 (bytes).
#define LSMA 0
#define LSMB 17408                 // A: 64*272
#define LTRG 52224                 // B: 128*272
#define LSM_BYTES (LTRG + 512 + 512 + 128)

__global__ void __launch_bounds__(512)
loss_mma_kernel(float* __restrict__ out)
{
    extern __shared__ char sm[];
    const uint32_t smb = smem_u32(sm);
    int* targ  = (int*)(sm + LTRG);
    int* tinfo = (int*)(sm + LTRG + 512);

    const int tid = threadIdx.x;
    const int l   = tid & 31;
    const int w   = tid >> 5;
    const int my  = w >> 3;          // 0..1
    const int cx  = w & 7;           // 0..7
    const int b   = blockIdx.x;

    int S, K, vl, chunk, mtile, qbase, pbase, aid0;
    if (b < 144) {
        int t = b / 72, rem = b % 72;
        vl = rem / 12;
        int r2 = rem % 12;
        mtile = r2 / 6; chunk = r2 % 6;
        S = 100; K = 50;
        qbase = t * 3600; pbase = t * 900;
        aid0  = t * 600 + vl * 100;
    } else {
        int bs = b - 144;
        int t2 = bs / 12;
        int rem = bs % 12;
        vl = rem / 2; chunk = rem % 2; mtile = 0;
        S = 20; K = 10;
        qbase = 7200 + t2 * 720; pbase = 1800 + t2 * 180;
        aid0  = 1200 + t2 * 120 + vl * 20;
    }
    const int NTARG = 6 * S + 3 * K;
    const int diag_base = qbase + vl * 7 * S;
    const int mrow0 = mtile * 64;

    if (tid < 128) {
        int n = chunk * 128 + tid;
        int row = 0, info = 0;
        if (n < 6 * S) {
            int xy = n / S, ts = n - xy * S;
            row  = qbase + (xy * 6 + vl) * S + ts;
            info = ts | ((xy == vl) ? 0x10000 : 0) | 0x40000;
        } else if (n < NTARG) {
            int cc = n - 6 * S;
            int o = cc / K, k = cc - o * K;
            row  = Q_ROWS + pbase + (o * 6 + vl) * K + k;
            info = 0x20000 | 0x40000;
        }
        targ[tid]  = row;
        tinfo[tid] = info;
    }
    __syncthreads();

    // A (64 anchors) and B (128 targets) e4m3 tiles (16 float4 per 256B row)
    for (int i = tid; i < 64 * 16; i += 512) {
        int r = i >> 4, q = i & 15;
        int gr = mrow0 + r;
        int arow = diag_base + (gr < S ? gr : 0);
        *(float4*)(sm + LSMA + r * FPITCH + q * 16) =
            ((const float4*)g_proj8)[(size_t)arow * 16 + q];
    }
    for (int i = tid; i < 128 * 16; i += 512) {
        int r = i >> 4, q = i & 15;
        *(float4*)(sm + LSMB + r * FPITCH + q * 16) =
            ((const float4*)g_proj8)[(size_t)targ[r] * 16 + q];
    }
    __syncthreads();

    const uint32_t a_base = smb + LSMA +
        (my * 32 + ((l >> 3) & 1) * 8 + (l & 7)) * FPITCH + (l >> 4) * 16;
    const uint32_t b_base = smb + LSMB +
        (cx * 16 + ((l >> 4) & 1) * 8 + (l & 7)) * FPITCH + ((l >> 3) & 1) * 16;

    float c[2][2][4];
    #pragma unroll
    for (int mt = 0; mt < 2; mt++)
        #pragma unroll
        for (int nt = 0; nt < 2; nt++)
            #pragma unroll
            for (int j = 0; j < 4; j++) c[mt][nt][j] = 0.f;

    #pragma unroll
    for (int kk = 0; kk < 8; kk++) {
        uint32_t a[8];
        ldsm_x4(a,     a_base + kk * 32);
        ldsm_x4(a + 4, a_base + kk * 32 + 16 * FPITCH);
        uint32_t b4[4];
        ldsm_x4(b4, b_base + kk * 32);
        mma16832fp8(c[0][0], a,     b4);
        mma16832fp8(c[1][0], a + 4, b4);
        mma16832fp8(c[0][1], a,     b4 + 2);
        mma16832fp8(c[1][1], a + 4, b4 + 2);
    }

    const int g  = l >> 2;
    const int q2 = (l & 3) * 2;
    float pacc[4] = {0.f, 0.f, 0.f, 0.f};
    float nacc[4] = {0.f, 0.f, 0.f, 0.f};

    int rowg[4];
    #pragma unroll
    for (int s = 0; s < 4; s++)
        rowg[s] = mrow0 + my * 32 + (s >> 1) * 16 + (s & 1) * 8 + g;

    #pragma unroll
    for (int nt = 0; nt < 2; nt++) {
        #pragma unroll
        for (int jl = 0; jl < 2; jl++) {
            int info = tinfo[cx * 16 + nt * 8 + q2 + jl];
            if (info & 0x40000) {
                int ts = info & 0xFFFF;
                #pragma unroll
                for (int mt = 0; mt < 2; mt++) {
                    #pragma unroll
                    for (int jh = 0; jh < 2; jh++) {
                        int s = mt * 2 + jh;
                        if (rowg[s] < S) {
                            float e = __expf(2.0f * c[mt][nt][jh * 2 + jl]);
                            if (info & 0x20000)        nacc[s] += e;
                            else if (info & 0x10000) { if (ts != rowg[s]) nacc[s] += e; }
                            else if (ts == rowg[s])    pacc[s] += e;
                        }
                    }
                }
            }
        }
    }

    #pragma unroll
    for (int s = 0; s < 4; s++) {
        pacc[s] += __shfl_xor_sync(0xffffffffu, pacc[s], 1);
        pacc[s] += __shfl_xor_sync(0xffffffffu, pacc[s], 2);
        nacc[s] += __shfl_xor_sync(0xffffffffu, nacc[s], 1);
        nacc[s] += __shfl_xor_sync(0xffffffffu, nacc[s], 2);
    }
    if ((l & 3) == 0) {
        #pragma unroll
        for (int s = 0; s < 4; s++) {
            if (rowg[s] < S) {
                if (pacc[s] != 0.f) atomicAdd(&g_pos[aid0 + rowg[s]], pacc[s]);
                if (nacc[s] != 0.f) atomicAdd(&g_neg[aid0 + rowg[s]], nacc[s]);
            }
        }
    }

    // ---- fused finalize ----
    __shared__ unsigned int is_last;
    __threadfence();
    __syncthreads();
    if (tid == 0)
        is_last = (atomicAdd(&g_ctr, 1u) == (unsigned)(gridDim.x - 1));
    __syncthreads();
    if (is_last) {
        float loc = 0.f;
        for (int i = tid; i < N_ANCHORS; i += 512) {
            float p = g_pos[i], n = g_neg[i];
            loc += -logf(p / (p + n));
        }
        loc += __shfl_xor_sync(0xffffffffu, loc, 16);
        loc += __shfl_xor_sync(0xffffffffu, loc, 8);
        loc += __shfl_xor_sync(0xffffffffu, loc, 4);
        loc += __shfl_xor_sync(0xffffffffu, loc, 2);
        loc += __shfl_xor_sync(0xffffffffu, loc, 1);
        float* red = (float*)(sm + LTRG + 1024);
        if (l == 0) red[w] = loc;
        __syncthreads();
        if (w == 0) {
            float s = (l < 16) ? red[l] : 0.f;
            s += __shfl_xor_sync(0xffffffffu, s, 8);
            s += __shfl_xor_sync(0xffffffffu, s, 4);
            s += __shfl_xor_sync(0xffffffffu, s, 2);
            s += __shfl_xor_sync(0xffffffffu, s, 1);
            if (l == 0) out[0] = s * (1.0f / 1440.0f);
        }
    }
}

// ---------------------------------------------------------------------------
extern "C" void kernel_launch(void* const* d_in, const int* in_sizes, int n_in,
                              void* d_out, int out_size)
{
    const float* E    = (const float*)d_in[0];
    const float* W1   = (const float*)d_in[1];
    const float* b1   = (const float*)d_in[2];
    const float* W2   = (const float*)d_in[3];
    const float* b2   = (const float*)d_in[4];
    const int*   idxp = (const int*)d_in[5];
    const int*   idxr = (const int*)d_in[6];
    const int*   negp = (const int*)d_in[7];
    const int*   negr = (const int*)d_in[8];
    float* out = (float*)d_out;
    (void)in_sizes; (void)n_in; (void)out_size;

    cudaFuncSetAttribute(proj_mma_kernel,
                         cudaFuncAttributeMaxDynamicSharedMemorySize, SM_BYTES);
    cudaFuncSetAttribute(loss_mma_kernel,
                         cudaFuncAttributeMaxDynamicSharedMemorySize, LSM_BYTES);

    proj_mma_kernel<<<PROJ_BLOCKS, 512, SM_BYTES>>>(E, W1, b1, W2, b2,
                                                    idxp, idxr, negp, negr);
    loss_mma_kernel<<<LOSS_BLOCKS, 512, LSM_BYTES>>>(out);
}